// round 7
// baseline (speedup 1.0000x reference)
#include <cuda_runtime.h>
#include <math.h>

// GraphTemporalRefiner — single fused kernel with in-grid producer/consumer.
//   xg = conv7(x);  w[b] from xl -> g_last -> q -> p -> w  (block s==0 of batch)
//   scores[b,n,t] = w[b,n] . xg[b,t]  (const cancels in softmax)
//   u[b,n] = split-softmax weighted sum of xg; last slice block per batch:
//   o = Vp u + vb; a = out_proj o; LN; gelu MLP -> out (B,2)
// All 512 blocks are guaranteed co-resident (launch_bounds(256,4), smem 42.5KB
// -> 5 blocks/SM), so flag spins cannot deadlock. Flags/counters are restored
// to zero by the tails, keeping graph replays deterministic.

namespace {
constexpr int Bn  = 32;
constexpr int Tn  = 1024;
constexpr int Dn  = 64;
constexpr int Hn  = 128;
constexpr int NHn = 4;
constexpr int SL  = 64;
constexpr int NS  = Tn / SL;    // 16
}

__device__ float g_w[Bn * NHn * Dn];
__device__ float g_Vp[Hn * Dn];
__device__ float g_vb[Hn];
__device__ float g_m[Bn * NHn * NS];
__device__ float g_l[Bn * NHn * NS];
__device__ float g_u[Bn * NHn * NS * Dn];
__device__ unsigned int g_cnt[Bn];
__device__ unsigned int g_vpc;
__device__ unsigned int g_done;
__device__ volatile int g_wflag[Bn];
__device__ volatile int g_vpflag;

__global__ void __launch_bounds__(256, 4) fused_kernel(
    const float* __restrict__ x,
    const float* __restrict__ theta_w,    // (128, 64)
    const float* __restrict__ theta_b,
    const float* __restrict__ in_proj_w,  // (384, 128)
    const float* __restrict__ in_proj_b,
    const float* __restrict__ out_proj_w, // (128, 128)
    const float* __restrict__ out_proj_b,
    const float* __restrict__ ln_g,
    const float* __restrict__ ln_b,
    const float* __restrict__ w1,
    const float* __restrict__ b1,
    const float* __restrict__ w2,
    const float* __restrict__ b2,
    float* __restrict__ out)
{
    const int s = blockIdx.x, b = blockIdx.y, tid = threadIdx.x;
    const int warp = tid >> 5, lane = tid & 31;
    const int t0 = s * SL;
    const float SCALE = 0.17677669529663687f;   // 1/sqrt(32)

    __shared__ float xr[(SL + 6) * Dn];   // raw x rows [t0-3, t0+SL+2]
    __shared__ float xg[SL][Dn + 1];
    __shared__ float sc[NHn][SL];
    __shared__ float sw[NHn][Dn];
    // producer-chain scratch
    __shared__ float sxl[Dn];
    __shared__ float s_g[Hn];
    __shared__ float s_q[Hn];
    __shared__ float s_p[NHn][Hn];
    // tail scratch
    __shared__ float s_ML[NHn][2];
    __shared__ float s_u[NHn * Dn];
    __shared__ float s_o[Hn];
    __shared__ float s_a[Hn];
    __shared__ float s_hid[Hn];
    __shared__ float s_mv[2];
    __shared__ int   s_last;

    // ==== producer: per-batch score-weight chain (block s==0) ==============
    if (s == 0) {
        if (tid < Dn) {                  // xl = conv at t = T-1
            float sum = 0.f, ws = 0.f;
#pragma unroll
            for (int dd = 0; dd < 4; dd++) {
                float wv = 1.0f / (1.0f + (float)dd);
                ws += wv;
                sum += wv * __ldg(&x[((size_t)b * Tn + (Tn - 1 - dd)) * Dn + tid]);
            }
            sxl[tid] = __fdividef(sum, ws);
        }
        __syncthreads();

        // g_last[i] = theta_b[i] + theta[i,:] . xl — warp per output
#pragma unroll
        for (int k = 0; k < 16; k++) {
            int i = warp + 8 * k;
            float acc = 0.f;
#pragma unroll
            for (int m = 0; m < 2; m++)
                acc += __ldg(&theta_w[i * Dn + lane + 32 * m]) * sxl[lane + 32 * m];
#pragma unroll
            for (int off = 16; off; off >>= 1)
                acc += __shfl_xor_sync(0xFFFFFFFFu, acc, off);
            if (lane == 0) s_g[i] = acc + theta_b[i];
        }
        __syncthreads();

        // q[i] = bq[i] + Wq[i,:] . g — warp per output
#pragma unroll
        for (int k = 0; k < 16; k++) {
            int i = warp + 8 * k;
            float acc = 0.f;
#pragma unroll
            for (int m = 0; m < 4; m++)
                acc += __ldg(&in_proj_w[i * Hn + lane + 32 * m]) * s_g[lane + 32 * m];
#pragma unroll
            for (int off = 16; off; off >>= 1)
                acc += __shfl_xor_sync(0xFFFFFFFFu, acc, off);
            if (lane == 0) s_q[i] = acc + in_proj_b[i];
        }
        __syncthreads();

        // p[n][c] = sum_j q[n32+j] * Wk[128+n32+j, c] — coalesced over c
#pragma unroll
        for (int k = 0; k < 2; k++) {
            int o = tid + k * 256;
            int n = o >> 7, c = o & (Hn - 1);
            float acc = 0.f;
#pragma unroll 8
            for (int j = 0; j < 32; j++)
                acc += s_q[n * 32 + j] * __ldg(&in_proj_w[(Hn + n * 32 + j) * Hn + c]);
            s_p[n][c] = acc;
        }
        __syncthreads();

        // w[n][d] = SCALE * p[n] . theta[:,d] — coalesced over d
        {
            int n = tid >> 6, d = tid & 63;
            float acc = 0.f;
#pragma unroll 8
            for (int c = 0; c < Hn; c++)
                acc += s_p[n][c] * __ldg(&theta_w[c * Dn + d]);
            g_w[b * (NHn * Dn) + tid] = acc * SCALE;
        }
        __threadfence();
        __syncthreads();
        if (tid == 0) g_wflag[b] = 1;
    }

    // ==== stage raw x rows (all blocks, float4 coalesced) ===================
    {
        const float4* xb4 = (const float4*)&x[(size_t)b * Tn * Dn];
        float4* xr4 = (float4*)xr;
        for (int i = tid; i < (SL + 6) * 16; i += 256) {
            int r = i >> 4, gt = t0 - 3 + r;
            if (gt >= 0 && gt < Tn) xr4[i] = __ldg(&xb4[gt * 16 + (i & 15)]);
        }
    }

    // ==== producer: Vp folding (blocks s==1, b<8; 16 rows each) =============
    if (s == 1 && b < 8) {
        const int r0 = b * 16;
#pragma unroll
        for (int k = 0; k < 4; k++) {
            int o = tid + k * 256;        // 1024 = 16*64
            int h = o >> 6, d = o & 63;
            float acc = 0.f;
#pragma unroll 8
            for (int c = 0; c < Hn; c++)
                acc += __ldg(&in_proj_w[(2 * Hn + r0 + h) * Hn + c]) *
                       __ldg(&theta_w[c * Dn + d]);
            g_Vp[(r0 + h) * Dn + d] = acc;
        }
        if (tid < 16) {
            float acc = in_proj_b[2 * Hn + r0 + tid];
#pragma unroll 8
            for (int c = 0; c < Hn; c++)
                acc += __ldg(&in_proj_w[(2 * Hn + r0 + tid) * Hn + c]) * theta_b[c];
            g_vb[r0 + tid] = acc;
        }
        __threadfence();
        __syncthreads();
        if (tid == 0) {
            unsigned int old = atomicAdd(&g_vpc, 1u);
            if (old == 7u) { __threadfence(); g_vpflag = 1; }
        }
    }

    // ==== consumers: wait for this batch's w ================================
    if (s != 0) {
        if (tid == 0) { while (g_wflag[b] == 0) __nanosleep(64); }
        __syncthreads();
        __threadfence();
    } else {
        __syncthreads();    // xr staged
    }
    sw[tid >> 6][tid & 63] = __ldg(&g_w[b * (NHn * Dn) + tid]);
    __syncthreads();

    // ==== conv from smem: xg[tl][d] =========================================
    for (int o = tid; o < SL * Dn; o += 256) {
        int tl = o >> 6, d = o & 63, t = t0 + tl;
        float sum = 0.f, ws = 0.f;
#pragma unroll
        for (int dd = -3; dd <= 3; dd++) {
            int tt = t + dd;
            if (tt >= 0 && tt < Tn) {
                float wv = 1.0f / (1.0f + (float)(dd < 0 ? -dd : dd));
                ws += wv;
                sum += wv * xr[(tl + 3 + dd) * Dn + d];
            }
        }
        xg[tl][d] = __fdividef(sum, ws);
    }
    __syncthreads();

    // ==== scores ============================================================
    {
        int n = tid >> 6, tl = tid & 63;
        float acc = 0.f;
#pragma unroll 8
        for (int d = 0; d < Dn; d++) acc += sw[n][d] * xg[tl][d];
        sc[n][tl] = acc;
    }
    __syncthreads();

    // ==== slice softmax partials: warp n = head n ===========================
    if (tid < NHn * 32) {
        int n = tid >> 5;
        float v0 = sc[n][lane], v1 = sc[n][lane + 32];
        float m = fmaxf(v0, v1);
#pragma unroll
        for (int off = 16; off; off >>= 1)
            m = fmaxf(m, __shfl_xor_sync(0xFFFFFFFFu, m, off));
        float e0 = __expf(v0 - m), e1 = __expf(v1 - m);
        sc[n][lane] = e0; sc[n][lane + 32] = e1;
        float l = e0 + e1;
#pragma unroll
        for (int off = 16; off; off >>= 1)
            l += __shfl_xor_sync(0xFFFFFFFFu, l, off);
        if (lane == 0) {
            g_m[(b * NHn + n) * NS + s] = m;
            g_l[(b * NHn + n) * NS + s] = l;
        }
    }
    __syncthreads();

    // ==== slice u partial ====================================================
    {
        int n = tid >> 6, d = tid & 63;
        float acc = 0.f;
#pragma unroll 4
        for (int t = 0; t < SL; t++) acc += sc[n][t] * xg[t][d];
        g_u[((b * NHn + n) * NS + s) * Dn + d] = acc;
    }

    // ==== last-block election ================================================
    __threadfence();
    __syncthreads();
    if (tid == 0) {
        unsigned int old = atomicAdd(&g_cnt[b], 1u);
        s_last = (old == NS - 1) ? 1 : 0;
    }
    __syncthreads();
    if (!s_last) return;
    __threadfence();

    // ==== tail for batch b ===================================================
    if (tid == 0) { while (g_vpflag == 0) __nanosleep(64); }
    __syncthreads();
    __threadfence();

    if (tid < NHn) {
        float M = -1e30f;
#pragma unroll
        for (int k = 0; k < NS; k++) M = fmaxf(M, g_m[(b * NHn + tid) * NS + k]);
        float L = 0.f;
#pragma unroll
        for (int k = 0; k < NS; k++)
            L += g_l[(b * NHn + tid) * NS + k] *
                 __expf(g_m[(b * NHn + tid) * NS + k] - M);
        s_ML[tid][0] = M;
        s_ML[tid][1] = L;
    }
    __syncthreads();
    {
        int n = tid >> 6, d = tid & 63;
        float acc = 0.f;
#pragma unroll
        for (int k = 0; k < NS; k++)
            acc += g_u[((b * NHn + n) * NS + k) * Dn + d] *
                   __expf(g_m[(b * NHn + n) * NS + k] - s_ML[n][0]);
        s_u[n * Dn + d] = __fdividef(acc, s_ML[n][1]);
    }
    __syncthreads();

    // o[i] = vb[i] + Vp[i,:] . u[i/32] — warp per output
#pragma unroll
    for (int k = 0; k < 16; k++) {
        int i = warp + 8 * k;
        int n = i >> 5;
        float acc = 0.f;
#pragma unroll
        for (int m = 0; m < 2; m++)
            acc += __ldg(&g_Vp[i * Dn + lane + 32 * m]) * s_u[n * Dn + lane + 32 * m];
#pragma unroll
        for (int off = 16; off; off >>= 1)
            acc += __shfl_xor_sync(0xFFFFFFFFu, acc, off);
        if (lane == 0) s_o[i] = acc + g_vb[i];
    }
    __syncthreads();

    // a[i] = ob[i] + out_proj[i,:] . o — warp per output
#pragma unroll
    for (int k = 0; k < 16; k++) {
        int i = warp + 8 * k;
        float acc = 0.f;
#pragma unroll
        for (int m = 0; m < 4; m++)
            acc += __ldg(&out_proj_w[i * Hn + lane + 32 * m]) * s_o[lane + 32 * m];
#pragma unroll
        for (int off = 16; off; off >>= 1)
            acc += __shfl_xor_sync(0xFFFFFFFFu, acc, off);
        if (lane == 0) s_a[i] = acc + out_proj_b[i];
    }
    __syncthreads();

    // LayerNorm over 128
    if (tid < 32) {
        float sum = s_a[tid] + s_a[tid + 32] + s_a[tid + 64] + s_a[tid + 96];
#pragma unroll
        for (int off = 16; off; off >>= 1)
            sum += __shfl_xor_sync(0xFFFFFFFFu, sum, off);
        if (tid == 0) s_mv[0] = sum * (1.0f / Hn);
    }
    __syncthreads();
    if (tid < 32) {
        float mu = s_mv[0], sum = 0.f;
#pragma unroll
        for (int k = 0; k < 4; k++) {
            float d = s_a[tid + 32 * k] - mu;
            sum += d * d;
        }
#pragma unroll
        for (int off = 16; off; off >>= 1)
            sum += __shfl_xor_sync(0xFFFFFFFFu, sum, off);
        if (tid == 0) s_mv[1] = sum * (1.0f / Hn);
    }
    __syncthreads();
    if (tid < Hn) {
        float inv = rsqrtf(s_mv[1] + 1e-5f);
        s_a[tid] = (s_a[tid] - s_mv[0]) * inv * ln_g[tid] + ln_b[tid];
    }
    __syncthreads();

    // hid = gelu(w1 @ ln + b1) — warp per output
#pragma unroll
    for (int k = 0; k < 16; k++) {
        int i = warp + 8 * k;
        float acc = 0.f;
#pragma unroll
        for (int m = 0; m < 4; m++)
            acc += __ldg(&w1[i * Hn + lane + 32 * m]) * s_a[lane + 32 * m];
#pragma unroll
        for (int off = 16; off; off >>= 1)
            acc += __shfl_xor_sync(0xFFFFFFFFu, acc, off);
        if (lane == 0) {
            float v = acc + b1[i];
            s_hid[i] = 0.5f * v * (1.0f + erff(v * 0.70710678118654752f));
        }
    }
    __syncthreads();

    if (warp < 2) {
        float acc = 0.f;
#pragma unroll
        for (int m = 0; m < 4; m++)
            acc += __ldg(&w2[warp * Hn + lane + 32 * m]) * s_hid[lane + 32 * m];
#pragma unroll
        for (int off = 16; off; off >>= 1)
            acc += __shfl_xor_sync(0xFFFFFFFFu, acc, off);
        if (lane == 0) out[b * 2 + warp] = acc + b2[warp];
    }

    // ==== restore flags/counters for next graph replay ======================
    __syncthreads();
    if (tid == 0) {
        g_cnt[b] = 0u;
        g_wflag[b] = 0;
        __threadfence();
        unsigned int old = atomicAdd(&g_done, 1u);
        if (old == (unsigned)(Bn - 1)) {
            g_vpflag = 0;
            g_vpc = 0u;
            g_done = 0u;
        }
    }
}

// ---------------------------------------------------------------------------
extern "C" void kernel_launch(void* const* d_in, const int* in_sizes, int n_in,
                              void* d_out, int out_size) {
    const float* x          = (const float*)d_in[0];
    const float* theta_w    = (const float*)d_in[1];
    const float* theta_b    = (const float*)d_in[2];
    const float* in_proj_w  = (const float*)d_in[3];
    const float* in_proj_b  = (const float*)d_in[4];
    const float* out_proj_w = (const float*)d_in[5];
    const float* out_proj_b = (const float*)d_in[6];
    const float* lng        = (const float*)d_in[7];
    const float* lnb        = (const float*)d_in[8];
    const float* w1         = (const float*)d_in[9];
    const float* b1         = (const float*)d_in[10];
    const float* w2         = (const float*)d_in[11];
    const float* b2         = (const float*)d_in[12];
    float* out = (float*)d_out;

    fused_kernel<<<dim3(NS, Bn), 256>>>(x, theta_w, theta_b, in_proj_w,
                                        in_proj_b, out_proj_w, out_proj_b,
                                        lng, lnb, w1, b1, w2, b2, out);
}

// round 8
// speedup vs baseline: 1.0747x; 1.0747x over previous
#include <cuda_runtime.h>
#include <math.h>

// GraphTemporalRefiner — conv commuted into scalar domain.
//   y[b,n,t]   = w[b,n] . x[b,t]           (4 dots per row)
//   score_t    = (1/rs(t)) sum_dd wv(|dd|) y_{t+dd}     (scalar 7-tap conv)
//   u_part     = sum_tau c_tau x_tau,  c = transpose-conv of phat/rs
//   tail: o = Vp u + vb; a = out_proj o; LN; gelu MLP -> out (B,2)
// pre (grid 40): per-batch w chain + Vp/vb folding (R6, proven).
// score (grid 16x32): scalar-domain slice body; last block per batch = tail.

namespace {
constexpr int Bn  = 32;
constexpr int Tn  = 1024;
constexpr int Dn  = 64;
constexpr int Hn  = 128;
constexpr int NHn = 4;
constexpr int SL  = 64;
constexpr int NS  = Tn / SL;    // 16
constexpr int NR  = SL + 6;     // 70 rows incl. halo
constexpr int RS  = 68;         // xr row stride (17 float4)
}

__device__ float g_w[Bn * NHn * Dn];
__device__ float g_Vp[Hn * Dn];
__device__ float g_vb[Hn];
__device__ float g_m[Bn * NHn * NS];
__device__ float g_l[Bn * NHn * NS];
__device__ float g_u[Bn * NHn * NS * Dn];
__device__ unsigned int g_cnt[Bn];

// ---------------------------------------------------------------------------
// pre: blocks 0..31 -> w[b]; blocks 32..39 -> Vp rows (16 each) + vb.
// ---------------------------------------------------------------------------
__global__ void __launch_bounds__(256) pre_kernel(
    const float* __restrict__ x,
    const float* __restrict__ theta_w,    // (128, 64)
    const float* __restrict__ theta_b,
    const float* __restrict__ in_proj_w,  // (384, 128)
    const float* __restrict__ in_proj_b)
{
    const int tid = threadIdx.x;
    const int warp = tid >> 5, lane = tid & 31;
    const float SCALE = 0.17677669529663687f;   // 1/sqrt(32)

    __shared__ float th[Hn * (Dn + 1)];   // padded theta

    for (int i = tid; i < Hn * Dn; i += 256)
        th[(i >> 6) * (Dn + 1) + (i & 63)] = theta_w[i];

    if (blockIdx.x < Bn) {
        const int b = blockIdx.x;
        __shared__ float sxl[Dn];
        __shared__ float s_g[Hn];
        __shared__ float s_q[Hn];
        __shared__ float s_p[NHn][Hn];

        if (tid == 0) g_cnt[b] = 0u;

        if (tid < Dn) {                   // xl = conv at t = T-1
            float sum = 0.f, ws = 0.f;
#pragma unroll
            for (int dd = 0; dd < 4; dd++) {
                float wv = 1.0f / (1.0f + (float)dd);
                ws += wv;
                sum += wv * __ldg(&x[((size_t)b * Tn + (Tn - 1 - dd)) * Dn + tid]);
            }
            sxl[tid] = __fdividef(sum, ws);
        }
        __syncthreads();

        if (tid < Hn) {                   // g_last
            float acc = theta_b[tid];
#pragma unroll 8
            for (int d = 0; d < Dn; d++) acc += th[tid * (Dn + 1) + d] * sxl[d];
            s_g[tid] = acc;
        }
        __syncthreads();

#pragma unroll
        for (int k = 0; k < 16; k++) {    // q — warp per output
            int i = warp + 8 * k;
            float acc = 0.f;
#pragma unroll
            for (int m = 0; m < 4; m++)
                acc += __ldg(&in_proj_w[i * Hn + lane + 32 * m]) * s_g[lane + 32 * m];
#pragma unroll
            for (int off = 16; off; off >>= 1)
                acc += __shfl_xor_sync(0xFFFFFFFFu, acc, off);
            if (lane == 0) s_q[i] = acc + in_proj_b[i];
        }
        __syncthreads();

#pragma unroll
        for (int k = 0; k < 2; k++) {     // p[n][c]
            int o = tid + k * 256;
            int n = o >> 7, c = o & (Hn - 1);
            float acc = 0.f;
#pragma unroll 8
            for (int j = 0; j < 32; j++)
                acc += s_q[n * 32 + j] * __ldg(&in_proj_w[(Hn + n * 32 + j) * Hn + c]);
            s_p[n][c] = acc;
        }
        __syncthreads();

        {                                 // w[n][d]
            int n = tid >> 6, d = tid & 63;
            float acc = 0.f;
#pragma unroll 8
            for (int c = 0; c < Hn; c++) acc += s_p[n][c] * th[c * (Dn + 1) + d];
            g_w[b * (NHn * Dn) + tid] = acc * SCALE;
        }
    } else {
        const int r0 = (blockIdx.x - Bn) * 16;
        __shared__ float s_wv[16 * Hn];
        for (int i = tid; i < 16 * Hn; i += 256)
            s_wv[i] = in_proj_w[(2 * Hn + r0) * Hn + i];
        __syncthreads();
#pragma unroll
        for (int k = 0; k < 4; k++) {
            int o = tid + k * 256;
            int h = o >> 6, d = o & 63;
            float acc = 0.f;
#pragma unroll 8
            for (int c = 0; c < Hn; c++)
                acc += s_wv[h * Hn + c] * th[c * (Dn + 1) + d];
            g_Vp[(r0 + h) * Dn + d] = acc;
        }
        if (tid < 16) {
            float acc = in_proj_b[2 * Hn + r0 + tid];
#pragma unroll 8
            for (int c = 0; c < Hn; c++)
                acc += s_wv[tid * Hn + c] * theta_b[c];
            g_vb[r0 + tid] = acc;
        }
    }
}

// ---------------------------------------------------------------------------
// score: grid (NS, Bn). Scalar-domain conv trick; last block = tail.
// ---------------------------------------------------------------------------
__global__ void __launch_bounds__(256) score_kernel(
    const float* __restrict__ x,
    const float* __restrict__ out_proj_w,
    const float* __restrict__ out_proj_b,
    const float* __restrict__ ln_g,
    const float* __restrict__ ln_b,
    const float* __restrict__ w1,
    const float* __restrict__ b1,
    const float* __restrict__ w2,
    const float* __restrict__ b2,
    float* __restrict__ out)
{
    const int s = blockIdx.x, b = blockIdx.y, tid = threadIdx.x;
    const int warp = tid >> 5, lane = tid & 31;
    const int t0 = s * SL;

    __shared__ float xr[NR * RS];        // raw x rows [t0-3, t0+SL+2], padded
    __shared__ float y[NHn][NR + 2];
    __shared__ float sc[NHn][SL];        // scores -> phat
    __shared__ float rsinv[SL];
    __shared__ float cc[NHn][NR];
    __shared__ float s_ML[NHn][2];
    __shared__ float s_u[NHn * Dn];
    __shared__ float s_o[Hn];
    __shared__ float s_a[Hn];
    __shared__ float s_hid[Hn];
    __shared__ float s_mv[2];
    __shared__ int   s_last;

    // stage raw x rows (float4 coalesced); OOB rows zeroed
    {
        const float4* xb4 = (const float4*)&x[(size_t)b * Tn * Dn];
        float4* xr4 = (float4*)xr;
        for (int i = tid; i < NR * 16; i += 256) {
            int r = i >> 4, c4 = i & 15, gt = t0 - 3 + r;
            float4 v = make_float4(0.f, 0.f, 0.f, 0.f);
            if (gt >= 0 && gt < Tn) v = __ldg(&xb4[gt * 16 + c4]);
            xr4[r * 17 + c4] = v;
        }
    }
    __syncthreads();

    // y[n][r] = w[n] . xr[r]  — warp-dots (2 warps per head, 35 rows each)
    {
        int n = warp >> 1, half = warp & 1;
        float w0 = __ldg(&g_w[b * 256 + n * Dn + lane]);
        float w1v = __ldg(&g_w[b * 256 + n * Dn + 32 + lane]);
#pragma unroll
        for (int jj = 0; jj < 35; jj++) {
            int r = half * 35 + jj;
            float acc = w0 * xr[r * RS + lane] + w1v * xr[r * RS + 32 + lane];
#pragma unroll
            for (int off = 16; off; off >>= 1)
                acc += __shfl_xor_sync(0xFFFFFFFFu, acc, off);
            if (lane == 0) y[n][r] = acc;
        }
    }
    __syncthreads();

    // score_t = (1/rs) sum_dd wv y[t+3+dd]; rsinv shared per t
    {
        int n = tid >> 6, t = tid & 63, tg = t0 + t;
        float acc = 0.f, ws = 0.f;
#pragma unroll
        for (int dd = -3; dd <= 3; dd++) {
            int tt = tg + dd;
            if (tt >= 0 && tt < Tn) {
                float wv = 1.0f / (1.0f + (float)(dd < 0 ? -dd : dd));
                ws += wv;
                acc += wv * y[n][t + 3 + dd];
            }
        }
        float inv = __fdividef(1.0f, ws);
        sc[n][t] = acc * inv;
        if (n == 0) rsinv[t] = inv;
    }
    __syncthreads();

    // slice softmax partials: warp n = head n; sc -> phat
    if (tid < NHn * 32) {
        int n = tid >> 5;
        float v0 = sc[n][lane], v1 = sc[n][lane + 32];
        float m = fmaxf(v0, v1);
#pragma unroll
        for (int off = 16; off; off >>= 1)
            m = fmaxf(m, __shfl_xor_sync(0xFFFFFFFFu, m, off));
        float e0 = __expf(v0 - m), e1 = __expf(v1 - m);
        sc[n][lane] = e0; sc[n][lane + 32] = e1;
        float l = e0 + e1;
#pragma unroll
        for (int off = 16; off; off >>= 1)
            l += __shfl_xor_sync(0xFFFFFFFFu, l, off);
        if (lane == 0) {
            g_m[(b * NHn + n) * NS + s] = m;
            g_l[(b * NHn + n) * NS + s] = l;
        }
    }
    __syncthreads();

    // c[n][i] = sum_dd wv * phat[j]*rsinv[j], j = i-3-dd  (transpose conv)
    for (int o = tid; o < NHn * NR; o += 256) {
        int n = o / NR, i = o % NR;
        int taug = t0 - 3 + i;
        float acc = 0.f;
        if (taug >= 0 && taug < Tn) {
#pragma unroll
            for (int dd = -3; dd <= 3; dd++) {
                int j = i - 3 - dd;
                if (j >= 0 && j < SL) {
                    float wv = 1.0f / (1.0f + (float)(dd < 0 ? -dd : dd));
                    acc += wv * sc[n][j] * rsinv[j];
                }
            }
        }
        cc[n][i] = acc;
    }
    __syncthreads();

    // u_part[n][d] = sum_i c[n][i] * xr[i][d]
    {
        int n = tid >> 6, d = tid & 63;
        float acc = 0.f;
#pragma unroll 7
        for (int i = 0; i < NR; i++) acc += cc[n][i] * xr[i * RS + d];
        g_u[((b * NHn + n) * NS + s) * Dn + d] = acc;
    }

    // ---- last-block election ------------------------------------------------
    __threadfence();
    __syncthreads();
    if (tid == 0) {
        unsigned int old = atomicAdd(&g_cnt[b], 1u);
        s_last = (old == NS - 1) ? 1 : 0;
    }
    __syncthreads();
    if (!s_last) return;
    __threadfence();

    // ---- tail for batch b -----------------------------------------------------
    if (tid < NHn) {
        float M = -1e30f;
#pragma unroll
        for (int k = 0; k < NS; k++) M = fmaxf(M, g_m[(b * NHn + tid) * NS + k]);
        float L = 0.f;
#pragma unroll
        for (int k = 0; k < NS; k++)
            L += g_l[(b * NHn + tid) * NS + k] *
                 __expf(g_m[(b * NHn + tid) * NS + k] - M);
        s_ML[tid][0] = M;
        s_ML[tid][1] = L;
    }
    __syncthreads();
    {
        int n = tid >> 6, d = tid & 63;
        float acc = 0.f;
#pragma unroll
        for (int k = 0; k < NS; k++)
            acc += g_u[((b * NHn + n) * NS + k) * Dn + d] *
                   __expf(g_m[(b * NHn + n) * NS + k] - s_ML[n][0]);
        s_u[n * Dn + d] = __fdividef(acc, s_ML[n][1]);
    }
    __syncthreads();

    // o[i] = vb[i] + Vp[i,:] . u[i/32] — warp per output
#pragma unroll
    for (int k = 0; k < 16; k++) {
        int i = warp + 8 * k;
        int n = i >> 5;
        float acc = 0.f;
#pragma unroll
        for (int m = 0; m < 2; m++)
            acc += __ldg(&g_Vp[i * Dn + lane + 32 * m]) * s_u[n * Dn + lane + 32 * m];
#pragma unroll
        for (int off = 16; off; off >>= 1)
            acc += __shfl_xor_sync(0xFFFFFFFFu, acc, off);
        if (lane == 0) s_o[i] = acc + g_vb[i];
    }
    __syncthreads();

    // a[i] = out_proj[i,:] . o + b — warp per output
#pragma unroll
    for (int k = 0; k < 16; k++) {
        int i = warp + 8 * k;
        float acc = 0.f;
#pragma unroll
        for (int m = 0; m < 4; m++)
            acc += __ldg(&out_proj_w[i * Hn + lane + 32 * m]) * s_o[lane + 32 * m];
#pragma unroll
        for (int off = 16; off; off >>= 1)
            acc += __shfl_xor_sync(0xFFFFFFFFu, acc, off);
        if (lane == 0) s_a[i] = acc + out_proj_b[i];
    }
    __syncthreads();

    // LayerNorm over 128
    if (tid < 32) {
        float sum = s_a[tid] + s_a[tid + 32] + s_a[tid + 64] + s_a[tid + 96];
#pragma unroll
        for (int off = 16; off; off >>= 1)
            sum += __shfl_xor_sync(0xFFFFFFFFu, sum, off);
        if (tid == 0) s_mv[0] = sum * (1.0f / Hn);
    }
    __syncthreads();
    if (tid < 32) {
        float mu = s_mv[0], sum = 0.f;
#pragma unroll
        for (int k = 0; k < 4; k++) {
            float d = s_a[tid + 32 * k] - mu;
            sum += d * d;
        }
#pragma unroll
        for (int off = 16; off; off >>= 1)
            sum += __shfl_xor_sync(0xFFFFFFFFu, sum, off);
        if (tid == 0) s_mv[1] = sum * (1.0f / Hn);
    }
    __syncthreads();
    if (tid < Hn) {
        float inv = rsqrtf(s_mv[1] + 1e-5f);
        s_a[tid] = (s_a[tid] - s_mv[0]) * inv * ln_g[tid] + ln_b[tid];
    }
    __syncthreads();

    // hid = gelu(w1 @ ln + b1) — warp per output
#pragma unroll
    for (int k = 0; k < 16; k++) {
        int i = warp + 8 * k;
        float acc = 0.f;
#pragma unroll
        for (int m = 0; m < 4; m++)
            acc += __ldg(&w1[i * Hn + lane + 32 * m]) * s_a[lane + 32 * m];
#pragma unroll
        for (int off = 16; off; off >>= 1)
            acc += __shfl_xor_sync(0xFFFFFFFFu, acc, off);
        if (lane == 0) {
            float v = acc + b1[i];
            s_hid[i] = 0.5f * v * (1.0f + erff(v * 0.70710678118654752f));
        }
    }
    __syncthreads();

    if (warp < 2) {
        float acc = 0.f;
#pragma unroll
        for (int m = 0; m < 4; m++)
            acc += __ldg(&w2[warp * Hn + lane + 32 * m]) * s_hid[lane + 32 * m];
#pragma unroll
        for (int off = 16; off; off >>= 1)
            acc += __shfl_xor_sync(0xFFFFFFFFu, acc, off);
        if (lane == 0) out[b * 2 + warp] = acc + b2[warp];
    }
}

// ---------------------------------------------------------------------------
extern "C" void kernel_launch(void* const* d_in, const int* in_sizes, int n_in,
                              void* d_out, int out_size) {
    const float* x          = (const float*)d_in[0];
    const float* theta_w    = (const float*)d_in[1];
    const float* theta_b    = (const float*)d_in[2];
    const float* in_proj_w  = (const float*)d_in[3];
    const float* in_proj_b  = (const float*)d_in[4];
    const float* out_proj_w = (const float*)d_in[5];
    const float* out_proj_b = (const float*)d_in[6];
    const float* lng        = (const float*)d_in[7];
    const float* lnb        = (const float*)d_in[8];
    const float* w1         = (const float*)d_in[9];
    const float* b1         = (const float*)d_in[10];
    const float* w2         = (const float*)d_in[11];
    const float* b2         = (const float*)d_in[12];
    float* out = (float*)d_out;

    pre_kernel<<<40, 256>>>(x, theta_w, theta_b, in_proj_w, in_proj_b);
    score_kernel<<<dim3(NS, Bn), 256>>>(x, out_proj_w, out_proj_b,
                                        lng, lnb, w1, b1, w2, b2, out);
}

// round 9
// speedup vs baseline: 1.1843x; 1.1020x over previous
#include <cuda_runtime.h>
#include <math.h>

// GraphTemporalRefiner — scalar-domain conv + dedicated prefetching tail block.
//   y[b,n,t] = w[b,n] . x[b,t];  score_t = (1/rs) sum wv*y_{t+dd}
//   u_part   = sum_tau c_tau x_tau   (c = transpose-conv of phat/rs)
//   tail: o = Vp u + vb; a = out_proj o; LN; gelu MLP -> out (B,2)
// pre (grid 40): per-batch w chain + Vp/vb folding.
// score (grid (NS+1) x 32): s<NS = slice blocks; s==NS = tail block that
//   L2-prefetches tail weights while spinning on the batch counter.

namespace {
constexpr int Bn  = 32;
constexpr int Tn  = 1024;
constexpr int Dn  = 64;
constexpr int Hn  = 128;
constexpr int NHn = 4;
constexpr int SL  = 64;
constexpr int NS  = Tn / SL;    // 16
constexpr int NR  = SL + 6;     // 70 rows incl. halo
constexpr int RS  = 71;         // xr scalar row stride (conflict-free: gcd(71%32=7,32)=1)
}

__device__ float g_w[Bn * NHn * Dn];
__device__ float g_Vp[Hn * Dn];
__device__ float g_vb[Hn];
__device__ float g_m[Bn * NHn * NS];
__device__ float g_l[Bn * NHn * NS];
__device__ float g_u[Bn * NHn * NS * Dn];
__device__ unsigned int g_cnt[Bn];

__device__ __forceinline__ void l2_prefetch(const void* p) {
    asm volatile("prefetch.global.L2 [%0];" :: "l"(p));
}

// ---------------------------------------------------------------------------
// pre: blocks 0..31 -> w[b]; blocks 32..39 -> Vp rows (16 each) + vb.
// ---------------------------------------------------------------------------
__global__ void __launch_bounds__(256) pre_kernel(
    const float* __restrict__ x,
    const float* __restrict__ theta_w,    // (128, 64)
    const float* __restrict__ theta_b,
    const float* __restrict__ in_proj_w,  // (384, 128)
    const float* __restrict__ in_proj_b)
{
    const int tid = threadIdx.x;
    const int warp = tid >> 5, lane = tid & 31;
    const float SCALE = 0.17677669529663687f;   // 1/sqrt(32)

    __shared__ float th[Hn * (Dn + 1)];

    for (int i = tid; i < Hn * Dn; i += 256)
        th[(i >> 6) * (Dn + 1) + (i & 63)] = theta_w[i];

    if (blockIdx.x < Bn) {
        const int b = blockIdx.x;
        __shared__ float sxl[Dn];
        __shared__ float s_g[Hn];
        __shared__ float s_q[Hn];
        __shared__ float s_p[NHn][Hn];

        if (tid == 0) g_cnt[b] = 0u;

        if (tid < Dn) {                   // xl = conv at t = T-1
            float sum = 0.f, ws = 0.f;
#pragma unroll
            for (int dd = 0; dd < 4; dd++) {
                float wv = 1.0f / (1.0f + (float)dd);
                ws += wv;
                sum += wv * __ldg(&x[((size_t)b * Tn + (Tn - 1 - dd)) * Dn + tid]);
            }
            sxl[tid] = __fdividef(sum, ws);
        }
        __syncthreads();

        if (tid < Hn) {                   // g_last
            float acc = theta_b[tid];
#pragma unroll 8
            for (int d = 0; d < Dn; d++) acc += th[tid * (Dn + 1) + d] * sxl[d];
            s_g[tid] = acc;
        }
        __syncthreads();

#pragma unroll
        for (int k = 0; k < 16; k++) {    // q — warp per output
            int i = warp + 8 * k;
            float acc = 0.f;
#pragma unroll
            for (int m = 0; m < 4; m++)
                acc += __ldg(&in_proj_w[i * Hn + lane + 32 * m]) * s_g[lane + 32 * m];
#pragma unroll
            for (int off = 16; off; off >>= 1)
                acc += __shfl_xor_sync(0xFFFFFFFFu, acc, off);
            if (lane == 0) s_q[i] = acc + in_proj_b[i];
        }
        __syncthreads();

#pragma unroll
        for (int k = 0; k < 2; k++) {     // p[n][c]
            int o = tid + k * 256;
            int n = o >> 7, c = o & (Hn - 1);
            float acc = 0.f;
#pragma unroll 8
            for (int j = 0; j < 32; j++)
                acc += s_q[n * 32 + j] * __ldg(&in_proj_w[(Hn + n * 32 + j) * Hn + c]);
            s_p[n][c] = acc;
        }
        __syncthreads();

        {                                 // w[n][d]
            int n = tid >> 6, d = tid & 63;
            float acc = 0.f;
#pragma unroll 8
            for (int c = 0; c < Hn; c++) acc += s_p[n][c] * th[c * (Dn + 1) + d];
            g_w[b * (NHn * Dn) + tid] = acc * SCALE;
        }
    } else {
        const int r0 = (blockIdx.x - Bn) * 16;
        __shared__ float s_wv[16 * Hn];
        for (int i = tid; i < 16 * Hn; i += 256)
            s_wv[i] = in_proj_w[(2 * Hn + r0) * Hn + i];
        __syncthreads();
#pragma unroll
        for (int k = 0; k < 4; k++) {
            int o = tid + k * 256;
            int h = o >> 6, d = o & 63;
            float acc = 0.f;
#pragma unroll 8
            for (int c = 0; c < Hn; c++)
                acc += s_wv[h * Hn + c] * th[c * (Dn + 1) + d];
            g_Vp[(r0 + h) * Dn + d] = acc;
        }
        if (tid < 16) {
            float acc = in_proj_b[2 * Hn + r0 + tid];
#pragma unroll 8
            for (int c = 0; c < Hn; c++)
                acc += s_wv[tid * Hn + c] * theta_b[c];
            g_vb[r0 + tid] = acc;
        }
    }
}

// ---------------------------------------------------------------------------
// score: grid (NS+1, Bn). s<NS = slice body; s==NS = dedicated tail block.
// ---------------------------------------------------------------------------
__global__ void __launch_bounds__(256) score_kernel(
    const float* __restrict__ x,
    const float* __restrict__ out_proj_w,
    const float* __restrict__ out_proj_b,
    const float* __restrict__ ln_g,
    const float* __restrict__ ln_b,
    const float* __restrict__ w1,
    const float* __restrict__ b1,
    const float* __restrict__ w2,
    const float* __restrict__ b2,
    float* __restrict__ out)
{
    const int s = blockIdx.x, b = blockIdx.y, tid = threadIdx.x;
    const int warp = tid >> 5, lane = tid & 31;

    __shared__ float xr[NR * RS];        // ~19.9 KB
    __shared__ float y[NHn][NR + 2];
    __shared__ float sc[NHn][SL];
    __shared__ float rsinv[SL];
    __shared__ float cc[NHn][NR];
    __shared__ float sw[NHn][Dn + 1];
    __shared__ float s_ML[NHn][2];
    __shared__ float s_u[NHn * Dn];
    __shared__ float s_o[Hn];
    __shared__ float s_a[Hn];
    __shared__ float s_hid[Hn];
    __shared__ float s_mv[2];

    if (s < NS) {
        // ===================== slice body =====================
        const int t0 = s * SL;

        // stage raw x rows -> scalar stride-71 smem; OOB zeroed
        {
            const float4* xb4 = (const float4*)&x[(size_t)b * Tn * Dn];
            for (int i = tid; i < NR * 16; i += 256) {
                int r = i >> 4, c4 = i & 15, gt = t0 - 3 + r;
                float4 v = make_float4(0.f, 0.f, 0.f, 0.f);
                if (gt >= 0 && gt < Tn) v = __ldg(&xb4[gt * 16 + c4]);
                int base = r * RS + c4 * 4;
                xr[base] = v.x; xr[base + 1] = v.y;
                xr[base + 2] = v.z; xr[base + 3] = v.w;
            }
        }
        sw[tid >> 6][tid & 63] = __ldg(&g_w[b * (NHn * Dn) + tid]);
        __syncthreads();

        // y[n][r] = w[n] . xr[r] — per-thread conflict-free dots
        for (int o = tid; o < NHn * NR; o += 256) {
            int n = o / NR, r = o - n * NR;
            float acc = 0.f;
#pragma unroll 8
            for (int d = 0; d < Dn; d++) acc += sw[n][d] * xr[r * RS + d];
            y[n][r] = acc;
        }
        __syncthreads();

        // score_t = (1/rs) sum_dd wv y[t+3+dd]
        {
            int n = tid >> 6, t = tid & 63, tg = t0 + t;
            float acc = 0.f, ws = 0.f;
#pragma unroll
            for (int dd = -3; dd <= 3; dd++) {
                int tt = tg + dd;
                if (tt >= 0 && tt < Tn) {
                    float wv = 1.0f / (1.0f + (float)(dd < 0 ? -dd : dd));
                    ws += wv;
                    acc += wv * y[n][t + 3 + dd];
                }
            }
            float inv = __fdividef(1.0f, ws);
            sc[n][t] = acc * inv;
            if (n == 0) rsinv[t] = inv;
        }
        __syncthreads();

        // slice softmax partials: warp n = head n; sc -> phat
        if (tid < NHn * 32) {
            int n = tid >> 5;
            float v0 = sc[n][lane], v1 = sc[n][lane + 32];
            float m = fmaxf(v0, v1);
#pragma unroll
            for (int off = 16; off; off >>= 1)
                m = fmaxf(m, __shfl_xor_sync(0xFFFFFFFFu, m, off));
            float e0 = __expf(v0 - m), e1 = __expf(v1 - m);
            sc[n][lane] = e0; sc[n][lane + 32] = e1;
            float l = e0 + e1;
#pragma unroll
            for (int off = 16; off; off >>= 1)
                l += __shfl_xor_sync(0xFFFFFFFFu, l, off);
            if (lane == 0) {
                g_m[(b * NHn + n) * NS + s] = m;
                g_l[(b * NHn + n) * NS + s] = l;
            }
        }
        __syncthreads();

        // c[n][i] = transpose-conv of phat*rsinv
        for (int o = tid; o < NHn * NR; o += 256) {
            int n = o / NR, i = o - n * NR;
            int taug = t0 - 3 + i;
            float acc = 0.f;
            if (taug >= 0 && taug < Tn) {
#pragma unroll
                for (int dd = -3; dd <= 3; dd++) {
                    int j = i - 3 - dd;
                    if (j >= 0 && j < SL) {
                        float wv = 1.0f / (1.0f + (float)(dd < 0 ? -dd : dd));
                        acc += wv * sc[n][j] * rsinv[j];
                    }
                }
            }
            cc[n][i] = acc;
        }
        __syncthreads();

        // u_part[n][d] = sum_i c[n][i] * xr[i][d]
        {
            int n = tid >> 6, d = tid & 63;
            float acc = 0.f;
#pragma unroll 7
            for (int i = 0; i < NR; i++) acc += cc[n][i] * xr[i * RS + d];
            g_u[((b * NHn + n) * NS + s) * Dn + d] = acc;
        }

        __threadfence();
        __syncthreads();
        if (tid == 0) atomicAdd(&g_cnt[b], 1u);
        return;
    }

    // ===================== dedicated tail block (s == NS) =====================
    // L2-prefetch tail weights while slices run
    {
        const char* p1 = (const char*)out_proj_w;    // 64 KB
        const char* p2 = (const char*)w1;            // 64 KB
        const char* p3 = (const char*)g_Vp;          // 32 KB
        for (int i = tid; i < 512; i += 256) { l2_prefetch(p1 + i * 128); l2_prefetch(p2 + i * 128); }
        for (int i = tid; i < 256; i += 256) l2_prefetch(p3 + i * 128);
        if (tid < 8) {
            l2_prefetch((const char*)g_vb + tid * 64);
            l2_prefetch((const char*)out_proj_b + tid * 64);
            l2_prefetch((const char*)ln_g + tid * 64);
            l2_prefetch((const char*)ln_b + tid * 64);
            l2_prefetch((const char*)b1 + tid * 64);
            l2_prefetch((const char*)w2 + tid * 64);
        }
    }

    // spin until all NS slice blocks of this batch have deposited partials
    if (tid == 0) {
        volatile unsigned int* cnt = &g_cnt[b];
        while (*cnt < (unsigned)NS) __nanosleep(128);
    }
    __syncthreads();
    __threadfence();   // acquire

    if (tid < NHn) {
        float M = -1e30f;
#pragma unroll
        for (int k = 0; k < NS; k++) M = fmaxf(M, g_m[(b * NHn + tid) * NS + k]);
        float L = 0.f;
#pragma unroll
        for (int k = 0; k < NS; k++)
            L += g_l[(b * NHn + tid) * NS + k] *
                 __expf(g_m[(b * NHn + tid) * NS + k] - M);
        s_ML[tid][0] = M;
        s_ML[tid][1] = L;
    }
    __syncthreads();
    {
        int n = tid >> 6, d = tid & 63;
        float acc = 0.f;
#pragma unroll
        for (int k = 0; k < NS; k++)
            acc += g_u[((b * NHn + n) * NS + k) * Dn + d] *
                   __expf(g_m[(b * NHn + n) * NS + k] - s_ML[n][0]);
        s_u[n * Dn + d] = __fdividef(acc, s_ML[n][1]);
    }
    __syncthreads();

    // o[i] = vb[i] + Vp[i,:] . u[i/32] — warp per output
#pragma unroll
    for (int k = 0; k < 16; k++) {
        int i = warp + 8 * k;
        int n = i >> 5;
        float acc = 0.f;
#pragma unroll
        for (int m = 0; m < 2; m++)
            acc += __ldg(&g_Vp[i * Dn + lane + 32 * m]) * s_u[n * Dn + lane + 32 * m];
#pragma unroll
        for (int off = 16; off; off >>= 1)
            acc += __shfl_xor_sync(0xFFFFFFFFu, acc, off);
        if (lane == 0) s_o[i] = acc + g_vb[i];
    }
    __syncthreads();

    // a[i] = out_proj[i,:] . o + b — warp per output
#pragma unroll
    for (int k = 0; k < 16; k++) {
        int i = warp + 8 * k;
        float acc = 0.f;
#pragma unroll
        for (int m = 0; m < 4; m++)
            acc += __ldg(&out_proj_w[i * Hn + lane + 32 * m]) * s_o[lane + 32 * m];
#pragma unroll
        for (int off = 16; off; off >>= 1)
            acc += __shfl_xor_sync(0xFFFFFFFFu, acc, off);
        if (lane == 0) s_a[i] = acc + out_proj_b[i];
    }
    __syncthreads();

    // LayerNorm over 128
    if (tid < 32) {
        float sum = s_a[tid] + s_a[tid + 32] + s_a[tid + 64] + s_a[tid + 96];
#pragma unroll
        for (int off = 16; off; off >>= 1)
            sum += __shfl_xor_sync(0xFFFFFFFFu, sum, off);
        if (tid == 0) s_mv[0] = sum * (1.0f / Hn);
    }
    __syncthreads();
    if (tid < 32) {
        float mu = s_mv[0], sum = 0.f;
#pragma unroll
        for (int k = 0; k < 4; k++) {
            float d = s_a[tid + 32 * k] - mu;
            sum += d * d;
        }
#pragma unroll
        for (int off = 16; off; off >>= 1)
            sum += __shfl_xor_sync(0xFFFFFFFFu, sum, off);
        if (tid == 0) s_mv[1] = sum * (1.0f / Hn);
    }
    __syncthreads();
    if (tid < Hn) {
        float inv = rsqrtf(s_mv[1] + 1e-5f);
        s_a[tid] = (s_a[tid] - s_mv[0]) * inv * ln_g[tid] + ln_b[tid];
    }
    __syncthreads();

    // hid = gelu(w1 @ ln + b1) — warp per output
#pragma unroll
    for (int k = 0; k < 16; k++) {
        int i = warp + 8 * k;
        float acc = 0.f;
#pragma unroll
        for (int m = 0; m < 4; m++)
            acc += __ldg(&w1[i * Hn + lane + 32 * m]) * s_a[lane + 32 * m];
#pragma unroll
        for (int off = 16; off; off >>= 1)
            acc += __shfl_xor_sync(0xFFFFFFFFu, acc, off);
        if (lane == 0) {
            float v = acc + b1[i];
            s_hid[i] = 0.5f * v * (1.0f + erff(v * 0.70710678118654752f));
        }
    }
    __syncthreads();

    if (warp < 2) {
        float acc = 0.f;
#pragma unroll
        for (int m = 0; m < 4; m++)
            acc += __ldg(&w2[warp * Hn + lane + 32 * m]) * s_hid[lane + 32 * m];
#pragma unroll
        for (int off = 16; off; off >>= 1)
            acc += __shfl_xor_sync(0xFFFFFFFFu, acc, off);
        if (lane == 0) out[b * 2 + warp] = acc + b2[warp];
    }

    // reset counter for next graph replay
    __syncthreads();
    if (tid == 0) g_cnt[b] = 0u;
}

// ---------------------------------------------------------------------------
extern "C" void kernel_launch(void* const* d_in, const int* in_sizes, int n_in,
                              void* d_out, int out_size) {
    const float* x          = (const float*)d_in[0];
    const float* theta_w    = (const float*)d_in[1];
    const float* theta_b    = (const float*)d_in[2];
    const float* in_proj_w  = (const float*)d_in[3];
    const float* in_proj_b  = (const float*)d_in[4];
    const float* out_proj_w = (const float*)d_in[5];
    const float* out_proj_b = (const float*)d_in[6];
    const float* lng        = (const float*)d_in[7];
    const float* lnb        = (const float*)d_in[8];
    const float* w1         = (const float*)d_in[9];
    const float* b1         = (const float*)d_in[10];
    const float* w2         = (const float*)d_in[11];
    const float* b2         = (const float*)d_in[12];
    float* out = (float*)d_out;

    pre_kernel<<<40, 256>>>(x, theta_w, theta_b, in_proj_w, in_proj_b);
    score_kernel<<<dim3(NS + 1, Bn), 256>>>(x, out_proj_w, out_proj_b,
                                            lng, lnb, w1, b1, w2, b2, out);
}